// round 1
// baseline (speedup 1.0000x reference)
#include <cuda_runtime.h>

#define IMG 224
#define NPIX (IMG * IMG)        // 50176
#define NUM_VIEWS 6
#define NBATCH 16
#define NPTS 32768
#define THREADS 1024

__global__ __launch_bounds__(THREADS, 1)
void render_kernel(const float* __restrict__ points, float* __restrict__ out) {
    extern __shared__ float simg[];          // NPIX floats (image accumulator)
    __shared__ float red_min[32], red_max[32];

    const int bv = blockIdx.x;
    const int b  = bv / NUM_VIEWS;
    const int v  = bv % NUM_VIEWS;
    const int tid = threadIdx.x;

    // View angles, matching the reference f32 computation
    const float deg2rad = 0.017453292519943295f;   // float(pi/180)
    const float a = (float)(v * 60) * deg2rad;
    const float el_tab[NUM_VIEWS] = {0.f, 30.f, -30.f, 0.f, 0.f, 0.f};
    const float e = el_tab[v] * deg2rad;
    const float ca = cosf(a), sa = sinf(a), ce = cosf(e), se = sinf(e);

    const float* __restrict__ pb = points + (size_t)b * NPTS * 3;

    // ---- Pass 1: zmin/zmax of z_fin over N, while zeroing the shared image ----
    float zmn =  INFINITY, zmx = -INFINITY;
    for (int n = tid; n < NPTS; n += THREADS) {
        float x = pb[3 * n + 0];
        float y = pb[3 * n + 1];
        float z = pb[3 * n + 2];
        float zr = x * sa + z * ca;
        float zf = y * se + zr * ce;
        zmn = fminf(zmn, zf);
        zmx = fmaxf(zmx, zf);
    }
    #pragma unroll
    for (int o = 16; o > 0; o >>= 1) {
        zmn = fminf(zmn, __shfl_xor_sync(0xffffffffu, zmn, o));
        zmx = fmaxf(zmx, __shfl_xor_sync(0xffffffffu, zmx, o));
    }
    const int wid = tid >> 5, lid = tid & 31;
    if (lid == 0) { red_min[wid] = zmn; red_max[wid] = zmx; }

    // zero image (int 0 == float 0.0)
    for (int i = tid; i < NPIX; i += THREADS) simg[i] = 0.0f;
    __syncthreads();

    if (wid == 0) {
        zmn = red_min[lid];
        zmx = red_max[lid];
        #pragma unroll
        for (int o = 16; o > 0; o >>= 1) {
            zmn = fminf(zmn, __shfl_xor_sync(0xffffffffu, zmn, o));
            zmx = fmaxf(zmx, __shfl_xor_sync(0xffffffffu, zmx, o));
        }
        if (lid == 0) { red_min[0] = zmn; red_max[0] = zmx; }
    }
    __syncthreads();
    zmn = red_min[0];
    zmx = red_max[0];
    const float den = zmx - zmn + 1e-6f;

    // ---- Pass 2: rotate + splat ----
    // The 25 offsets span [off0, off4] per axis with 0.498-pixel steps, so the
    // set of hit pixels is exactly the integer rectangle between the endpoint
    // pixel coords (monotone truncation, step <= 1 pixel).
    const float off0 = -2.0f / 224.0f;
    const float off4 =  2.0f / 224.0f;
    int* iimg = (int*)simg;

    for (int n = tid; n < NPTS; n += THREADS) {
        float x = pb[3 * n + 0];
        float y = pb[3 * n + 1];
        float z = pb[3 * n + 2];
        float xr = x * ca - z * sa;
        float zr = x * sa + z * ca;
        float yr = y * ce - zr * se;
        float zf = y * se + zr * ce;

        float feat = 0.3f + 0.7f * (zf - zmn) / den;   // in [0.3, 1.0]

        // endpoint pixel coords, computed exactly like the reference
        int px0 = (int)((xr + off0 + 1.0f) * 0.5f * (float)(IMG - 1));
        int px4 = (int)((xr + off4 + 1.0f) * 0.5f * (float)(IMG - 1));
        int py0 = (int)((yr + off0 + 1.0f) * 0.5f * (float)(IMG - 1));
        int py4 = (int)((yr + off4 + 1.0f) * 0.5f * (float)(IMG - 1));

        int xlo = max(px0, 0), xhi = min(px4, IMG - 1);
        int ylo = max(py0, 0), yhi = min(py4, IMG - 1);
        if (xlo > xhi || ylo > yhi) continue;

        const int fb = __float_as_int(feat);           // positive floats order as ints
        for (int q = ylo; q <= yhi; q++) {
            int rowbase = q * IMG;
            for (int p = xlo; p <= xhi; p++) {
                atomicMax(&iimg[rowbase + p], fb);
            }
        }
    }
    __syncthreads();

    // ---- Epilogue: broadcast image to 3 channels of out[b][v][c][h][w] ----
    float* __restrict__ ob = out + (size_t)bv * 3 * NPIX;
    for (int i = tid; i < NPIX; i += THREADS) {
        float val = __int_as_float(iimg[i]);
        ob[i]             = val;
        ob[NPIX + i]      = val;
        ob[2 * NPIX + i]  = val;
    }
}

extern "C" void kernel_launch(void* const* d_in, const int* in_sizes, int n_in,
                              void* d_out, int out_size) {
    const float* points = (const float*)d_in[0];
    float* out = (float*)d_out;

    const size_t smem = (size_t)NPIX * sizeof(float);  // 200704 bytes
    cudaFuncSetAttribute(render_kernel,
                         cudaFuncAttributeMaxDynamicSharedMemorySize, (int)smem);

    render_kernel<<<NBATCH * NUM_VIEWS, THREADS, smem>>>(points, out);
}